// round 8
// baseline (speedup 1.0000x reference)
#include <cuda_runtime.h>
#include <cstdint>
#include <cstddef>

// ---------------- problem constants ----------------
#define NUM_HEADS 8
#define DHEAD 32
#define BLOCK_SZ 8
#define HALO 3
#define WIN 14          // BLOCK + 2*HALO
#define WINP 196        // WIN*WIN
#define NHB 12          // 96/8
#define NB 144          // 12*12
#define HW 96
#define SPATIAL 9216    // 96*96
#define BATCH 8
#define CIN 256
#define OQKV 768        // 256 q + 512 kv
#define SCALE 0.17677669529663687f
#define LOG2E 1.4426950408889634f

typedef unsigned long long u64;

// ---- f32x2 packed-math helpers (Blackwell dual-rate fp32) ----
__device__ __forceinline__ u64 pack2(float lo, float hi) {
    u64 r; asm("mov.b64 %0, {%1, %2};" : "=l"(r) : "f"(lo), "f"(hi)); return r;
}
__device__ __forceinline__ void unpack2(u64 v, float& lo, float& hi) {
    asm("mov.b64 {%0, %1}, %2;" : "=f"(lo), "=f"(hi) : "l"(v));
}
__device__ __forceinline__ void fma2(u64& d, u64 a, u64 b) {
    asm("fma.rn.f32x2 %0, %1, %2, %0;" : "+l"(d) : "l"(a), "l"(b));
}
__device__ __forceinline__ void mul2(u64& d, u64 a) {
    asm("mul.rn.f32x2 %0, %0, %1;" : "+l"(d) : "l"(a));
}
__device__ __forceinline__ u64 add2(u64 a, u64 b) {
    u64 r; asm("add.rn.f32x2 %0, %1, %2;" : "=l"(r) : "l"(a), "l"(b)); return r;
}

// scratch: qkv[b][o][s], o<256 -> q (head*32+d), o>=256 -> kv (256 + head*64 + c)
__device__ float g_qkv[(size_t)BATCH * OQKV * SPATIAL];

// ---------------- kernel 1: fused QKV projection GEMM ----------------
// tile 128x128, BK=16, 256 threads, 8x8 micro-tile, FFMA2 with B dup packs.
// Double-buffered smem: ONE __syncthreads per k-tile.
#define GBM 128
#define GBN 128
#define GBK 16
#define APAD 132   // As row stride (words)

__global__ void __launch_bounds__(256, 2) qkv_gemm(
    const float* __restrict__ x,
    const float* __restrict__ qw,
    const float* __restrict__ kvw)
{
    __shared__ float As[2][GBK][APAD];   // [stage][k][m]
    __shared__ float Bs[2][GBK][GBN];    // [stage][k][n]

    const int b  = blockIdx.z;
    const int m0 = blockIdx.y * GBM;
    const int n0 = blockIdx.x * GBN;
    const int tid = threadIdx.x;

    const float* xb = x + (size_t)b * CIN * SPATIAL;

    const int tr = tid >> 4;          // 0..15
    const int tc = tid & 15;          // 0..15

    const int a_row0 = tid >> 2;
    const int a_ck   = (tid & 3) * 4;
    const int b_kr0  = tid >> 5;
    const int b_col  = (tid & 31) * 4;

    const float* wrowp[2];
#pragma unroll
    for (int i = 0; i < 2; i++) {
        const int o = m0 + a_row0 + i * 64;
        wrowp[i] = (o < 256) ? (qw + (size_t)o * CIN) : (kvw + (size_t)(o - 256) * CIN);
    }

    u64 acc2[4][8];
#pragma unroll
    for (int i = 0; i < 4; i++)
#pragma unroll
        for (int j = 0; j < 8; j++) acc2[i][j] = 0ULL;

    float4 pa[2], pb[2];
    // prefetch + commit tile 0 into stage 0
#pragma unroll
    for (int i = 0; i < 2; i++) {
        pa[i] = *(const float4*)(wrowp[i] + 0 + a_ck);
        pb[i] = *(const float4*)(xb + (size_t)(0 + b_kr0 + i * 8) * SPATIAL + n0 + b_col);
    }
#pragma unroll
    for (int i = 0; i < 2; i++) {
        const int ar = a_row0 + i * 64;
        As[0][a_ck + 0][ar] = pa[i].x;
        As[0][a_ck + 1][ar] = pa[i].y;
        As[0][a_ck + 2][ar] = pa[i].z;
        As[0][a_ck + 3][ar] = pa[i].w;
        *(float4*)&Bs[0][b_kr0 + i * 8][b_col] = pb[i];
    }
    __syncthreads();

    int s = 0;
    for (int k0 = 0; k0 < CIN; k0 += GBK) {
        const bool has_next = (k0 + GBK < CIN);
        if (has_next) {
#pragma unroll
            for (int i = 0; i < 2; i++) {
                pa[i] = *(const float4*)(wrowp[i] + k0 + GBK + a_ck);
                pb[i] = *(const float4*)(xb + (size_t)(k0 + GBK + b_kr0 + i * 8) * SPATIAL + n0 + b_col);
            }
        }

#pragma unroll
        for (int k = 0; k < GBK; k++) {
            ulonglong2 a01 = *(const ulonglong2*)&As[s][k][tr * 8];
            ulonglong2 a23 = *(const ulonglong2*)&As[s][k][tr * 8 + 4];
            u64 a2[4] = {a01.x, a01.y, a23.x, a23.y};
            float4 b0 = *(const float4*)&Bs[s][k][tc * 8];
            float4 b1 = *(const float4*)&Bs[s][k][tc * 8 + 4];
            u64 bd[8];
            bd[0] = pack2(b0.x, b0.x); bd[1] = pack2(b0.y, b0.y);
            bd[2] = pack2(b0.z, b0.z); bd[3] = pack2(b0.w, b0.w);
            bd[4] = pack2(b1.x, b1.x); bd[5] = pack2(b1.y, b1.y);
            bd[6] = pack2(b1.z, b1.z); bd[7] = pack2(b1.w, b1.w);
#pragma unroll
            for (int i = 0; i < 4; i++)
#pragma unroll
                for (int j = 0; j < 8; j++)
                    fma2(acc2[i][j], a2[i], bd[j]);
        }

        if (has_next) {
            const int ns = s ^ 1;
#pragma unroll
            for (int i = 0; i < 2; i++) {
                const int ar = a_row0 + i * 64;
                As[ns][a_ck + 0][ar] = pa[i].x;
                As[ns][a_ck + 1][ar] = pa[i].y;
                As[ns][a_ck + 2][ar] = pa[i].z;
                As[ns][a_ck + 3][ar] = pa[i].w;
                *(float4*)&Bs[ns][b_kr0 + i * 8][b_col] = pb[i];
            }
        }
        __syncthreads();
        s ^= 1;
    }

    float* outb = g_qkv + (size_t)b * OQKV * SPATIAL;
#pragma unroll
    for (int i = 0; i < 4; i++) {
        float lo[8], hi[8];
#pragma unroll
        for (int j = 0; j < 8; j++) unpack2(acc2[i][j], lo[j], hi[j]);
        const int r0 = m0 + tr * 8 + 2 * i;
        float* p0 = outb + (size_t)r0 * SPATIAL + n0 + tc * 8;
        float* p1 = p0 + SPATIAL;
        *(float4*)(p0)     = make_float4(lo[0], lo[1], lo[2], lo[3]);
        *(float4*)(p0 + 4) = make_float4(lo[4], lo[5], lo[6], lo[7]);
        *(float4*)(p1)     = make_float4(hi[0], hi[1], hi[2], hi[3]);
        *(float4*)(p1 + 4) = make_float4(hi[4], hi[5], hi[6], hi[7]);
    }
}

// ---------------- kernel 2: halo attention ----------------
// 256 threads/block: thread = q*4 + quad. Each thread: 1 query, 7x7 quadrant
// of the 14x14 window. 4 partials combined via lane shuffles (xor 1, xor 2).
// 2 blocks/SM (16 warps). Log2-domain softmax, f32x2 math throughout.
#define KV_STRIDE 68                         // 64 ch + pad
#define SMEM_KV   (WINP * KV_STRIDE)         // 13328 floats
#define RELSTRIDE 36
#define SMEM_REL  (27 * RELSTRIDE)
#define SMEM_FLOATS (SMEM_KV + 2 * SMEM_REL)
#define SMEM_BYTES  (SMEM_FLOATS * 4)

__global__ void __launch_bounds__(256, 2) halo_attn(
    const float* __restrict__ hrel,
    const float* __restrict__ wrel,
    float* __restrict__ out)
{
    extern __shared__ float smem[];
    float* sKV = smem;                       // [196][68] : c<32 K, c>=32 V
    float* sH  = smem + SMEM_KV;             // [27][36]
    float* sW  = sH + SMEM_REL;              // [27][36]

    const int tid = threadIdx.x;
    const int nbidx = blockIdx.x;            // 0..143
    const int bh = blockIdx.y;               // 0..63
    const int b = bh >> 3, head = bh & 7;
    const int by = nbidx / NHB, bx = nbidx % NHB;

    // ---- stage rel tables ----
    for (int idx = tid; idx < 27 * 32; idx += 256) {
        const int r = idx >> 5, d = idx & 31;
        sH[r * RELSTRIDE + d] = hrel[idx];
        sW[r * RELSTRIDE + d] = wrel[idx];
    }

    // ---- stage KV window: thread owns one position, tight c loop ----
    const float* kvbase = g_qkv + ((size_t)b * OQKV + 256 + head * 64) * SPATIAL;
    if (tid < WINP) {
        const int y = tid / WIN, xx = tid % WIN;
        const int gh = by * BLOCK_SZ + y - HALO;
        const int gw = bx * BLOCK_SZ + xx - HALO;
        const bool ok = ((unsigned)gh < (unsigned)HW) && ((unsigned)gw < (unsigned)HW);
        const float* src = kvbase + gh * HW + gw;
        float* dst = sKV + tid * KV_STRIDE;
#pragma unroll 8
        for (int c = 0; c < 64; c++)
            dst[c] = ok ? src[(size_t)c * SPATIAL] : 0.f;
    }

    // ---- per-thread assignment ----
    const int q    = tid >> 2;               // 0..63
    const int quad = tid & 3;
    const int y0 = (quad >> 1) * 7;
    const int x0 = (quad & 1) * 7;
    const int qi = q >> 3, qj = q & 7;
    const int sp = (by * BLOCK_SZ + qi) * HW + bx * BLOCK_SZ + qj;

    // ---- load Q row as f32x2 d-pairs, pre-scaled by LOG2E ----
    const float* qbase = g_qkv + ((size_t)b * OQKV + head * DHEAD) * SPATIAL + sp;
    u64 q2[16];
    const u64 le2 = pack2(LOG2E, LOG2E);
#pragma unroll
    for (int dd = 0; dd < 16; dd++) {
        q2[dd] = pack2(qbase[(size_t)(2 * dd) * SPATIAL], qbase[(size_t)(2 * dd + 1) * SPATIAL]);
        mul2(q2[dd], le2);
    }

    __syncthreads();

    // ---- relative position terms (log2 domain via q) ----
    float rw[7];
#pragma unroll
    for (int i = 0; i < 7; i++) {
        const ulonglong2* wr = (const ulonglong2*)&sW[(13 + x0 + i - qj) * RELSTRIDE];
        u64 s0 = 0ULL, s1 = 0ULL;
#pragma unroll
        for (int m = 0; m < 8; m++) {
            ulonglong2 wv = wr[m];
            fma2(s0, q2[2 * m],     wv.x);
            fma2(s1, q2[2 * m + 1], wv.y);
        }
        float l0, h0; unpack2(add2(s0, s1), l0, h0);
        rw[i] = l0 + h0;
    }
    float rh[7];
#pragma unroll
    for (int i = 0; i < 7; i++) {
        const ulonglong2* hr = (const ulonglong2*)&sH[(13 + y0 + i - qi) * RELSTRIDE];
        u64 s0 = 0ULL, s1 = 0ULL;
#pragma unroll
        for (int m = 0; m < 8; m++) {
            ulonglong2 hv = hr[m];
            fma2(s0, q2[2 * m],     hv.x);
            fma2(s1, q2[2 * m + 1], hv.y);
        }
        float l0, h0; unpack2(add2(s0, s1), l0, h0);
        rh[i] = l0 + h0;
    }
    // fold QK scale into q (total factor LOG2E * SCALE)
    const u64 sc2 = pack2(SCALE, SCALE);
#pragma unroll
    for (int dd = 0; dd < 16; dd++) mul2(q2[dd], sc2);

    // ---- flash loop over the 7x7 quadrant ----
    float m = -1e30f, l = 0.f;
    u64 acc2[16];
#pragma unroll
    for (int dd = 0; dd < 16; dd++) acc2[dd] = 0ULL;

    for (int yy = 0; yy < 7; yy++) {
        const float* kvp = sKV + ((y0 + yy) * WIN + x0) * KV_STRIDE;
        const float rhv = rh[yy];
        float lg[7];
#pragma unroll
        for (int xx = 0; xx < 7; xx++) {
            const ulonglong2* kp = (const ulonglong2*)(kvp + xx * KV_STRIDE);
            u64 s0 = 0ULL, s1 = 0ULL;
#pragma unroll
            for (int mm = 0; mm < 8; mm++) {
                ulonglong2 kv = kp[mm];
                fma2(s0, q2[2 * mm],     kv.x);
                fma2(s1, q2[2 * mm + 1], kv.y);
            }
            float l0, h0; unpack2(add2(s0, s1), l0, h0);
            lg[xx] = l0 + h0 + rhv + rw[xx];
        }
        // tree max (depth 3)
        float t0 = fmaxf(lg[0], lg[1]);
        float t1 = fmaxf(lg[2], lg[3]);
        float t2 = fmaxf(lg[4], lg[5]);
        const float rowm = fmaxf(fmaxf(t0, t1), fmaxf(t2, lg[6]));

        const float mnew = fmaxf(m, rowm);
        const float corr = exp2f(m - mnew);
        m = mnew;

        // batched independent exp2s (bare MUFU.EX2)
#pragma unroll
        for (int xx = 0; xx < 7; xx++) lg[xx] = exp2f(lg[xx] - mnew);

        float u0 = lg[0] + lg[1], u1 = lg[2] + lg[3], u2 = lg[4] + lg[5];
        l = l * corr + ((u0 + u1) + (u2 + lg[6]));

        const u64 c2 = pack2(corr, corr);
#pragma unroll
        for (int dd = 0; dd < 16; dd++) mul2(acc2[dd], c2);

#pragma unroll
        for (int xx = 0; xx < 7; xx++) {
            const u64 p2 = pack2(lg[xx], lg[xx]);
            const ulonglong2* vp = (const ulonglong2*)(kvp + xx * KV_STRIDE + 32);
#pragma unroll
            for (int mm = 0; mm < 8; mm++) {
                ulonglong2 vv = vp[mm];
                fma2(acc2[2 * mm],     p2, vv.x);
                fma2(acc2[2 * mm + 1], p2, vv.y);
            }
        }
    }

    // ---- combine 4 quadrant partials via lane shuffles ----
    const unsigned FULL = 0xFFFFFFFFu;
    float M = m;
    M = fmaxf(M, __shfl_xor_sync(FULL, M, 1));
    M = fmaxf(M, __shfl_xor_sync(FULL, M, 2));
    const float w = exp2f(m - M);
    float lw = l * w;
    lw += __shfl_xor_sync(FULL, lw, 1);
    lw += __shfl_xor_sync(FULL, lw, 2);
    const float inv = 1.f / lw;

    float* ob = out + ((size_t)b * 256 + head * DHEAD) * SPATIAL + sp;
#pragma unroll
    for (int dd = 0; dd < 16; dd++) {
        float f0, f1; unpack2(acc2[dd], f0, f1);
        f0 *= w; f1 *= w;
        f0 += __shfl_xor_sync(FULL, f0, 1);
        f0 += __shfl_xor_sync(FULL, f0, 2);
        f1 += __shfl_xor_sync(FULL, f1, 1);
        f1 += __shfl_xor_sync(FULL, f1, 2);
        if (quad == 0) {
            ob[(size_t)(2 * dd) * SPATIAL]     = f0 * inv;
            ob[(size_t)(2 * dd + 1) * SPATIAL] = f1 * inv;
        }
    }
}

// ---------------- launch ----------------
extern "C" void kernel_launch(void* const* d_in, const int* in_sizes, int n_in,
                              void* d_out, int out_size)
{
    const float* x    = (const float*)d_in[0];
    const float* qw   = (const float*)d_in[1];
    const float* kvw  = (const float*)d_in[2];
    const float* hrel = (const float*)d_in[3];
    const float* wrel = (const float*)d_in[4];
    float* out = (float*)d_out;

    cudaFuncSetAttribute(halo_attn, cudaFuncAttributeMaxDynamicSharedMemorySize,
                         SMEM_BYTES);

    qkv_gemm<<<dim3(SPATIAL / GBN, OQKV / GBM, BATCH), 256>>>(x, qw, kvw);
    halo_attn<<<dim3(NB, BATCH * NUM_HEADS), 256, SMEM_BYTES>>>(hrel, wrel, out);
}

// round 9
// speedup vs baseline: 1.3790x; 1.3790x over previous
#include <cuda_runtime.h>
#include <cstdint>
#include <cstddef>

// ---------------- problem constants ----------------
#define NUM_HEADS 8
#define DHEAD 32
#define BLOCK_SZ 8
#define HALO 3
#define WIN 14          // BLOCK + 2*HALO
#define WINP 196        // WIN*WIN
#define NHB 12          // 96/8
#define NB 144          // 12*12
#define HW 96
#define SPATIAL 9216    // 96*96
#define BATCH 8
#define CIN 256
#define OQKV 768        // 256 q + 512 kv
#define SCALE 0.17677669529663687f
#define LOG2E 1.4426950408889634f

typedef unsigned long long u64;

// ---- f32x2 packed-math helpers (Blackwell dual-rate fp32) ----
__device__ __forceinline__ u64 pack2(float lo, float hi) {
    u64 r; asm("mov.b64 %0, {%1, %2};" : "=l"(r) : "f"(lo), "f"(hi)); return r;
}
__device__ __forceinline__ void unpack2(u64 v, float& lo, float& hi) {
    asm("mov.b64 {%0, %1}, %2;" : "=f"(lo), "=f"(hi) : "l"(v));
}
__device__ __forceinline__ void fma2(u64& d, u64 a, u64 b) {
    asm("fma.rn.f32x2 %0, %1, %2, %0;" : "+l"(d) : "l"(a), "l"(b));
}
__device__ __forceinline__ void mul2(u64& d, u64 a) {
    asm("mul.rn.f32x2 %0, %0, %1;" : "+l"(d) : "l"(a));
}
__device__ __forceinline__ u64 add2(u64 a, u64 b) {
    u64 r; asm("add.rn.f32x2 %0, %1, %2;" : "=l"(r) : "l"(a), "l"(b)); return r;
}
__device__ __forceinline__ unsigned smem_u32(const void* p) {
    unsigned a;
    asm("{ .reg .u64 t; cvta.to.shared.u64 t, %1; cvt.u32.u64 %0, t; }"
        : "=r"(a) : "l"(p));
    return a;
}
#define CP_ASYNC16(dst_u32, src) \
    asm volatile("cp.async.cg.shared.global [%0], [%1], 16;" :: "r"(dst_u32), "l"(src))
#define CP_COMMIT() asm volatile("cp.async.commit_group;")
#define CP_WAIT1()  asm volatile("cp.async.wait_group 1;" ::: "memory")

// scratch
__device__ float g_qkv[(size_t)BATCH * OQKV * SPATIAL];
__device__ float g_wt[(size_t)CIN * OQKV];   // W transposed: [k][o]

// ---------------- kernel 0: weight transpose (one-time, ~8us) ----------------
__global__ void __launch_bounds__(1024) wt_kernel(
    const float* __restrict__ qw, const float* __restrict__ kvw)
{
    __shared__ float t[32][33];
    const int o0 = blockIdx.x * 32;   // 24 blocks
    const int k0 = blockIdx.y * 32;   // 8 blocks
    const int o = o0 + threadIdx.y;
    const int k = k0 + threadIdx.x;
    const float* src = (o < 256) ? (qw + (size_t)o * CIN) : (kvw + (size_t)(o - 256) * CIN);
    t[threadIdx.y][threadIdx.x] = src[k];
    __syncthreads();
    g_wt[(size_t)(k0 + threadIdx.y) * OQKV + o0 + threadIdx.x] = t[threadIdx.x][threadIdx.y];
}

// ---------------- kernel 1: QKV GEMM, cp.async 3-stage pipeline ----------------
// C[b][o][s] = sum_k Wt[k][o] * x[b][k][s].  Tile 128x128, BK=16, 256 threads,
// 8x8 micro-tile, FFMA2 with B dup packs.
#define GBM 128
#define GBN 128
#define GBK 16
#define NSTAGE 3
#define NT (CIN / GBK)   // 16 tiles

__global__ void __launch_bounds__(256, 2) qkv_gemm(const float* __restrict__ x)
{
    __shared__ float As[NSTAGE][GBK][GBM];   // [k][m]  8KB/stage
    __shared__ float Bs[NSTAGE][GBK][GBN];   // [k][n]  8KB/stage

    const int b  = blockIdx.z;
    const int m0 = blockIdx.y * GBM;
    const int n0 = blockIdx.x * GBN;
    const int tid = threadIdx.x;

    const float* xb = x + (size_t)b * CIN * SPATIAL;

    const int tr = tid >> 4;          // 0..15
    const int tc = tid & 15;          // 0..15

    // chunk mapping: 512 16B-chunks per stage-tile per matrix; 2 per thread
    const int c0 = tid, c1 = tid + 256;
    const int kkA0 = c0 >> 5, offA0 = (c0 & 31) * 4;
    const int kkA1 = c1 >> 5, offA1 = (c1 & 31) * 4;

    u64 acc2[4][8];
#pragma unroll
    for (int i = 0; i < 4; i++)
#pragma unroll
        for (int j = 0; j < 8; j++) acc2[i][j] = 0ULL;

    // stage loader
    auto load_stage = [&](int s, int t) {
        const int k0 = t * GBK;
        unsigned dA0 = smem_u32(&As[s][kkA0][offA0]);
        unsigned dA1 = smem_u32(&As[s][kkA1][offA1]);
        unsigned dB0 = smem_u32(&Bs[s][kkA0][offA0]);
        unsigned dB1 = smem_u32(&Bs[s][kkA1][offA1]);
        CP_ASYNC16(dA0, g_wt + (size_t)(k0 + kkA0) * OQKV + m0 + offA0);
        CP_ASYNC16(dA1, g_wt + (size_t)(k0 + kkA1) * OQKV + m0 + offA1);
        CP_ASYNC16(dB0, xb + (size_t)(k0 + kkA0) * SPATIAL + n0 + offA0);
        CP_ASYNC16(dB1, xb + (size_t)(k0 + kkA1) * SPATIAL + n0 + offA1);
    };

    // prologue: tiles 0,1
    load_stage(0, 0); CP_COMMIT();
    load_stage(1, 1); CP_COMMIT();

    for (int t = 0; t < NT; t++) {
        CP_WAIT1();              // group for tile t complete (t+1 still pending)
        __syncthreads();         // all threads' data visible; stage (t+2)%3 free
        if (t + 2 < NT) load_stage((t + 2) % NSTAGE, t + 2);
        CP_COMMIT();             // always commit (possibly empty) to keep count
        const int s = t % NSTAGE;

#pragma unroll
        for (int k = 0; k < GBK; k++) {
            ulonglong2 a01 = *(const ulonglong2*)&As[s][k][tr * 8];
            ulonglong2 a23 = *(const ulonglong2*)&As[s][k][tr * 8 + 4];
            u64 a2[4] = {a01.x, a01.y, a23.x, a23.y};
            float4 b0 = *(const float4*)&Bs[s][k][tc * 8];
            float4 b1 = *(const float4*)&Bs[s][k][tc * 8 + 4];
            u64 bd[8];
            bd[0] = pack2(b0.x, b0.x); bd[1] = pack2(b0.y, b0.y);
            bd[2] = pack2(b0.z, b0.z); bd[3] = pack2(b0.w, b0.w);
            bd[4] = pack2(b1.x, b1.x); bd[5] = pack2(b1.y, b1.y);
            bd[6] = pack2(b1.z, b1.z); bd[7] = pack2(b1.w, b1.w);
#pragma unroll
            for (int i = 0; i < 4; i++)
#pragma unroll
                for (int j = 0; j < 8; j++)
                    fma2(acc2[i][j], a2[i], bd[j]);
        }
    }

    float* outb = g_qkv + (size_t)b * OQKV * SPATIAL;
#pragma unroll
    for (int i = 0; i < 4; i++) {
        float lo[8], hi[8];
#pragma unroll
        for (int j = 0; j < 8; j++) unpack2(acc2[i][j], lo[j], hi[j]);
        const int r0 = m0 + tr * 8 + 2 * i;
        float* p0 = outb + (size_t)r0 * SPATIAL + n0 + tc * 8;
        float* p1 = p0 + SPATIAL;
        *(float4*)(p0)     = make_float4(lo[0], lo[1], lo[2], lo[3]);
        *(float4*)(p0 + 4) = make_float4(lo[4], lo[5], lo[6], lo[7]);
        *(float4*)(p1)     = make_float4(hi[0], hi[1], hi[2], hi[3]);
        *(float4*)(p1 + 4) = make_float4(hi[4], hi[5], hi[6], hi[7]);
    }
}

// ---------------- kernel 2: halo attention (round-7, best known: 592us) ----
#define KV_STRIDE 68                         // 64 ch + pad
#define SMEM_KV   (WINP * KV_STRIDE)         // 13328 floats
#define RELSTRIDE 36
#define SMEM_REL  (27 * RELSTRIDE)
#define SMEM_FLOATS (SMEM_KV + 2 * SMEM_REL)
#define SMEM_BYTES  (SMEM_FLOATS * 4)

__global__ void __launch_bounds__(128) halo_attn(
    const float* __restrict__ hrel,
    const float* __restrict__ wrel,
    float* __restrict__ out)
{
    extern __shared__ float smem[];
    float* sKV = smem;                       // [196][68] : c<32 K, c>=32 V
    float* sH  = smem + SMEM_KV;             // [27][36]
    float* sW  = sH + SMEM_REL;              // [27][36]

    const int tid = threadIdx.x;
    const int nbidx = blockIdx.x;            // 0..143
    const int bh = blockIdx.y;               // 0..63
    const int b = bh >> 3, head = bh & 7;
    const int by = nbidx / NHB, bx = nbidx % NHB;

    // ---- stage rel tables ----
    for (int idx = tid; idx < 27 * 32; idx += 128) {
        const int r = idx >> 5, d = idx & 31;
        sH[r * RELSTRIDE + d] = hrel[idx];
        sW[r * RELSTRIDE + d] = wrel[idx];
    }

    // ---- stage KV window: thread owns 1-2 positions, tight c loop ----
    const float* kvbase = g_qkv + ((size_t)b * OQKV + 256 + head * 64) * SPATIAL;
#pragma unroll
    for (int rep = 0; rep < 2; rep++) {
        const int p = tid + rep * 128;
        if (p < WINP) {
            const int y = p / WIN, xx = p % WIN;
            const int gh = by * BLOCK_SZ + y - HALO;
            const int gw = bx * BLOCK_SZ + xx - HALO;
            const bool ok = ((unsigned)gh < (unsigned)HW) && ((unsigned)gw < (unsigned)HW);
            const float* src = kvbase + gh * HW + gw;
            float* dst = sKV + p * KV_STRIDE;
#pragma unroll 8
            for (int c = 0; c < 64; c++)
                dst[c] = ok ? src[(size_t)c * SPATIAL] : 0.f;
        }
    }

    // ---- load Q row as f32x2 d-pairs, pre-scaled by LOG2E ----
    const int q    = tid >> 1;
    const int half = tid & 1;
    const int qi = q >> 3, qj = q & 7;
    const int sp = (by * BLOCK_SZ + qi) * HW + bx * BLOCK_SZ + qj;
    const float* qbase = g_qkv + ((size_t)b * OQKV + head * DHEAD) * SPATIAL + sp;

    u64 q2[16];
    const u64 le2 = pack2(LOG2E, LOG2E);
#pragma unroll
    for (int dd = 0; dd < 16; dd++) {
        q2[dd] = pack2(qbase[(size_t)(2 * dd) * SPATIAL], qbase[(size_t)(2 * dd + 1) * SPATIAL]);
        mul2(q2[dd], le2);
    }

    __syncthreads();

    // ---- relative position terms (log2 domain via q) ----
    float rw[14];
#pragma unroll
    for (int xx = 0; xx < 14; xx++) {
        const ulonglong2* wr = (const ulonglong2*)&sW[(13 + xx - qj) * RELSTRIDE];
        u64 s0 = 0ULL, s1 = 0ULL;
#pragma unroll
        for (int m = 0; m < 8; m++) {
            ulonglong2 wv = wr[m];
            fma2(s0, q2[2 * m],     wv.x);
            fma2(s1, q2[2 * m + 1], wv.y);
        }
        float l0, h0; unpack2(add2(s0, s1), l0, h0);
        rw[xx] = l0 + h0;
    }
    const int y0 = half * 7;
    float rh[7];
#pragma unroll
    for (int yy = 0; yy < 7; yy++) {
        const ulonglong2* hr = (const ulonglong2*)&sH[(13 + y0 + yy - qi) * RELSTRIDE];
        u64 s0 = 0ULL, s1 = 0ULL;
#pragma unroll
        for (int m = 0; m < 8; m++) {
            ulonglong2 hv = hr[m];
            fma2(s0, q2[2 * m],     hv.x);
            fma2(s1, q2[2 * m + 1], hv.y);
        }
        float l0, h0; unpack2(add2(s0, s1), l0, h0);
        rh[yy] = l0 + h0;
    }
    // fold QK scale into q (total factor = LOG2E * SCALE)
    const u64 sc2 = pack2(SCALE, SCALE);
#pragma unroll
    for (int dd = 0; dd < 16; dd++) mul2(q2[dd], sc2);

    // ---- flash loop over this half's 7 window rows (log2-domain softmax) ----
    float m = -1e30f, l = 0.f;
    u64 acc2[16];
#pragma unroll
    for (int dd = 0; dd < 16; dd++) acc2[dd] = 0ULL;

    for (int yy = 0; yy < 7; yy++) {
        const float* kvp = sKV + (y0 + yy) * WIN * KV_STRIDE;
        const float rhv = rh[yy];
        float lg[14];
#pragma unroll
        for (int xx = 0; xx < 14; xx++) {
            const ulonglong2* kp = (const ulonglong2*)(kvp + xx * KV_STRIDE);
            u64 s0 = 0ULL, s1 = 0ULL;
#pragma unroll
            for (int mm = 0; mm < 8; mm++) {
                ulonglong2 kv = kp[mm];
                fma2(s0, q2[2 * mm],     kv.x);
                fma2(s1, q2[2 * mm + 1], kv.y);
            }
            float l0, h0; unpack2(add2(s0, s1), l0, h0);
            lg[xx] = l0 + h0 + rhv + rw[xx];
        }
        // tree max (depth 4)
        float t0 = fmaxf(lg[0], lg[1]),  t1 = fmaxf(lg[2], lg[3]);
        float t2 = fmaxf(lg[4], lg[5]),  t3 = fmaxf(lg[6], lg[7]);
        float t4 = fmaxf(lg[8], lg[9]),  t5 = fmaxf(lg[10], lg[11]);
        float t6 = fmaxf(lg[12], lg[13]);
        t0 = fmaxf(t0, t1); t2 = fmaxf(t2, t3); t4 = fmaxf(t4, t5);
        const float rowm = fmaxf(fmaxf(t0, t2), fmaxf(t4, t6));

        const float mnew = fmaxf(m, rowm);
        const float corr = exp2f(m - mnew);
        m = mnew;

        // batched independent exp2s (bare MUFU.EX2)
#pragma unroll
        for (int xx = 0; xx < 14; xx++) lg[xx] = exp2f(lg[xx] - mnew);

        float u0 = lg[0] + lg[1],   u1 = lg[2] + lg[3];
        float u2 = lg[4] + lg[5],   u3 = lg[6] + lg[7];
        float u4 = lg[8] + lg[9],   u5 = lg[10] + lg[11];
        float u6 = lg[12] + lg[13];
        l = l * corr + ((u0 + u1) + (u2 + u3)) + ((u4 + u5) + u6);

        const u64 c2 = pack2(corr, corr);
#pragma unroll
        for (int dd = 0; dd < 16; dd++) mul2(acc2[dd], c2);

#pragma unroll
        for (int xx = 0; xx < 14; xx++) {
            const u64 p2 = pack2(lg[xx], lg[xx]);
            const ulonglong2* vp = (const ulonglong2*)(kvp + xx * KV_STRIDE + 32);
#pragma unroll
            for (int mm = 0; mm < 8; mm++) {
                ulonglong2 vv = vp[mm];
                fma2(acc2[2 * mm],     p2, vv.x);
                fma2(acc2[2 * mm + 1], p2, vv.y);
            }
        }
    }

    // ---- combine the two halves (adjacent lanes) via shuffle ----
    const unsigned FULL = 0xFFFFFFFFu;
    const float m2 = __shfl_xor_sync(FULL, m, 1);
    const float M  = fmaxf(m, m2);
    const float w  = exp2f(m - M);
    const float lw = l * w;
    const float L  = lw + __shfl_xor_sync(FULL, lw, 1);
    const float inv = 1.0f / L;

    float* ob = out + ((size_t)b * 256 + head * DHEAD) * SPATIAL + sp;
#pragma unroll
    for (int dd = 0; dd < 16; dd++) {
        float f0, f1; unpack2(acc2[dd], f0, f1);
        f0 *= w; f1 *= w;
        f0 += __shfl_xor_sync(FULL, f0, 1);
        f1 += __shfl_xor_sync(FULL, f1, 1);
        if (half == 0) {
            ob[(size_t)(2 * dd) * SPATIAL]     = f0 * inv;
            ob[(size_t)(2 * dd + 1) * SPATIAL] = f1 * inv;
        }
    }
}

// ---------------- launch ----------------
extern "C" void kernel_launch(void* const* d_in, const int* in_sizes, int n_in,
                              void* d_out, int out_size)
{
    const float* x    = (const float*)d_in[0];
    const float* qw   = (const float*)d_in[1];
    const float* kvw  = (const float*)d_in[2];
    const float* hrel = (const float*)d_in[3];
    const float* wrel = (const float*)d_in[4];
    float* out = (float*)d_out;

    cudaFuncSetAttribute(halo_attn, cudaFuncAttributeMaxDynamicSharedMemorySize,
                         SMEM_BYTES);

    wt_kernel<<<dim3(OQKV / 32, CIN / 32), dim3(32, 32)>>>(qw, kvw);
    qkv_gemm<<<dim3(SPATIAL / GBN, OQKV / GBM, BATCH), 256>>>(x);
    halo_attn<<<dim3(NB, BATCH * NUM_HEADS), 128, SMEM_BYTES>>>(hrel, wrel, out);
}